// round 6
// baseline (speedup 1.0000x reference)
#include <cuda_runtime.h>
#include <cuda_bf16.h>

#define NN    1500
#define NEDGE 24000
#define EDIM  64
#define LOOPN 10

#define NBLK  148
#define TPB   512
#define NT_NODE 24          // ceil(1500/64)
#define NT_EDGE 375         // 24000/64

// ---------------- device scratch (static, allocation-free) ----------------
__device__ float g_vc[NN * 8];
__device__ float g_goal[8];
__device__ float g_x[NN * EDIM];
__device__ float g_y[NEDGE * EDIM];
__device__ float g_P[NN * EDIM];
__device__ float g_Q[NN * EDIM];
__device__ float g_agg[NN * EDIM];
__device__ float g_A1[EDIM * EDIM], g_B1[EDIM * EDIM];
__device__ float g_A2[EDIM * EDIM], g_B2[EDIM * EDIM];
__device__ float g_Ay[8 * EDIM],   g_By[8 * EDIM];
__device__ int   g_winner[NN * NN];   // 9 MB

// grid barrier state
__device__ unsigned g_count;
__device__ volatile unsigned g_gen;

#define NEG_INF __int_as_float(0xff800000)

__device__ __forceinline__ void atomicMaxFloat(float* addr, float val) {
    if (val >= 0.0f) atomicMax((int*)addr, __float_as_int(val));
    else             atomicMin((unsigned int*)addr, __float_as_uint(val));
}

// packed f32x2 FMA:  d = a*b + d  (two lanes)
__device__ __forceinline__ void ffma2(unsigned long long& d, unsigned long long a,
                                      unsigned long long b) {
    asm("fma.rn.f32x2 %0, %1, %2, %0;" : "+l"(d) : "l"(a), "l"(b));
}
__device__ __forceinline__ unsigned long long pack2(float v) {
    unsigned long long r;
    asm("mov.b64 %0, {%1, %1};" : "=l"(r) : "f"(v));
    return r;
}

// grid-wide barrier (all NBLK blocks resident; __threadfence emits CCTL.IVALL
// on sm_103a -> flushes L1D on both release and acquire sides)
__device__ __forceinline__ void gsync() {
    __syncthreads();
    if (threadIdx.x == 0) {
        unsigned gen = g_gen;
        __threadfence();
        if (atomicAdd(&g_count, 1u) == NBLK - 1) {
            g_count = 0;
            __threadfence();
            g_gen = gen + 1;
        } else {
            while (g_gen == gen) { }
        }
        __threadfence();
    }
    __syncthreads();
}

// ---------------- prep kernels ----------------

__global__ void k_vc(const float* __restrict__ v, const float* __restrict__ labels) {
    int i = blockIdx.x * blockDim.x + threadIdx.x;
    if (i < NN) {
        #pragma unroll
        for (int j = 0; j < 7; j++) g_vc[i * 8 + j] = v[i * 7 + j];
        g_vc[i * 8 + 7] = labels[i];
    }
}

__global__ void k_goal(const float* __restrict__ labels) {
    __shared__ float bv[256];
    __shared__ int   bi[256];
    int t = threadIdx.x;
    float best = -1e30f; int idx = 0;
    for (int i = t; i < NN; i += 256) {
        float l = labels[i];
        if (l > best) { best = l; idx = i; }
    }
    bv[t] = best; bi[t] = idx;
    __syncthreads();
    for (int s = 128; s > 0; s >>= 1) {
        if (t < s) {
            if (bv[t + s] > bv[t] || (bv[t + s] == bv[t] && bi[t + s] < bi[t])) {
                bv[t] = bv[t + s]; bi[t] = bi[t + s];
            }
        }
        __syncthreads();
    }
    if (t < 8) g_goal[t] = g_vc[bi[0] * 8 + t];
}

__global__ void k_wprep(const float* __restrict__ fxW1, const float* __restrict__ fyW1,
                        const float* __restrict__ hyW1) {
    int t = blockIdx.x * blockDim.x + threadIdx.x;
    if (t < 4096) {
        g_A1[t] = fxW1[t] + fxW1[4096 + t];
        g_B1[t] = fxW1[8192 + t] - fxW1[t];
        g_A2[t] = fyW1[t] + fyW1[4096 + t];
        g_B2[t] = fyW1[8192 + t] - fyW1[t];
        if (t < 512) {
            g_Ay[t] = hyW1[t] + hyW1[512 + t];
            g_By[t] = hyW1[1024 + t] - hyW1[t];
        }
    }
}

__global__ void k_init_x(const float* __restrict__ W1, const float* __restrict__ b1,
                         const float* __restrict__ W2, const float* __restrict__ b2) {
    int i = blockIdx.x;
    int c = threadIdx.x;                 // 64 threads
    __shared__ float z[32], h[64];
    if (c < 8) {
        float vcv = g_vc[i * 8 + c];
        float gl  = g_goal[c];
        float d   = vcv - gl;
        z[c] = vcv; z[8 + c] = gl; z[16 + c] = d; z[24 + c] = d * d;
    }
    __syncthreads();
    float acc = b1[c];
    #pragma unroll
    for (int k = 0; k < 32; k++) acc += z[k] * W1[k * 64 + c];
    h[c] = fmaxf(acc, 0.0f);
    __syncthreads();
    float o = b2[c];
    #pragma unroll 16
    for (int k = 0; k < 64; k++) o += h[k] * W2[k * 64 + c];
    g_x[i * 64 + c] = o;
}

__global__ void k_node8() {
    int i = blockIdx.x, c = threadIdx.x;   // 64 threads
    __shared__ float z[8];
    if (c < 8) z[c] = g_vc[i * 8 + c];
    __syncthreads();
    float r = 0.f, s = 0.f;
    #pragma unroll
    for (int k = 0; k < 8; k++) {
        r += z[k] * g_Ay[k * 64 + c];
        s += z[k] * g_By[k * 64 + c];
    }
    g_P[i * 64 + c] = r;
    g_Q[i * 64 + c] = s;
}

// initial y:  h = relu(P[tgt] + Q[src] + b1); y = h@W2 + b2
__global__ void k_edge_y0(const float* __restrict__ b1, const float* __restrict__ W2,
                          const float* __restrict__ b2,
                          const int* __restrict__ src, const int* __restrict__ tgt) {
    __shared__ float Ws[4096];
    __shared__ float hs[64 * 33];
    int tid = threadIdx.x;
    int e0  = blockIdx.x * 32;
    for (int idx = tid; idx < 4096; idx += 256) Ws[idx] = W2[idx];
    int el = tid >> 3, cg = tid & 7, c0 = cg * 8;
    int e = e0 + el;
    int s = src[e], t = tgt[e];
    #pragma unroll
    for (int j = 0; j < 8; j++) {
        float h = g_P[t * 64 + c0 + j] + g_Q[s * 64 + c0 + j] + b1[c0 + j];
        hs[(c0 + j) * 33 + el] = fmaxf(h, 0.f);
    }
    __syncthreads();
    unsigned long long acc2[4];
    acc2[0] = ((const ulonglong2*)&Ws[0])->x;   // dummy init, overwritten below
    {
        const float* bb = b2;
        float2 b01 = make_float2(bb[c0 + 0], bb[c0 + 1]);
        float2 b23 = make_float2(bb[c0 + 2], bb[c0 + 3]);
        float2 b45 = make_float2(bb[c0 + 4], bb[c0 + 5]);
        float2 b67 = make_float2(bb[c0 + 6], bb[c0 + 7]);
        acc2[0] = *(unsigned long long*)&b01;
        acc2[1] = *(unsigned long long*)&b23;
        acc2[2] = *(unsigned long long*)&b45;
        acc2[3] = *(unsigned long long*)&b67;
    }
    #pragma unroll 8
    for (int k = 0; k < 64; k++) {
        unsigned long long hv = pack2(hs[k * 33 + el]);
        ulonglong2 wa = *(const ulonglong2*)&Ws[k * 64 + c0];
        ulonglong2 wb = *(const ulonglong2*)&Ws[k * 64 + c0 + 4];
        ffma2(acc2[0], hv, wa.x); ffma2(acc2[1], hv, wa.y);
        ffma2(acc2[2], hv, wb.x); ffma2(acc2[3], hv, wb.y);
    }
    *(float4*)&g_y[e * 64 + c0]     = *(float4*)&acc2[0];
    *(float4*)&g_y[e * 64 + c0 + 4] = *(float4*)&acc2[2];
}

// ---------------- fused persistent loop kernel ----------------
// smem layout (floats):
//   A1 B1 A2 B2 Wy W2x W2y : 7 * 4096
//   bx1 bx2 by1 by2        : 4 * 64
//   ys, hs                 : 2 * 64*65
#define SM_A1  0
#define SM_B1  (SM_A1 + 4096)
#define SM_A2  (SM_B1 + 4096)
#define SM_B2  (SM_A2 + 4096)
#define SM_WY  (SM_B2 + 4096)
#define SM_W2X (SM_WY + 4096)
#define SM_W2Y (SM_W2X + 4096)
#define SM_BX1 (SM_W2Y + 4096)
#define SM_BX2 (SM_BX1 + 64)
#define SM_BY1 (SM_BX2 + 64)
#define SM_BY2 (SM_BY1 + 64)
#define SM_YS  (SM_BY2 + 64)
#define SM_HS  (SM_YS + 64 * 65)
#define SM_FLOATS (SM_HS + 64 * 65)

__global__ void __launch_bounds__(TPB, 1)
k_loop(const float* __restrict__ fxW1y, const float* __restrict__ fx_b1,
       const float* __restrict__ fx_W2, const float* __restrict__ fx_b2,
       const float* __restrict__ fy_b1, const float* __restrict__ fy_W2,
       const float* __restrict__ fy_b2,
       const int* __restrict__ src, const int* __restrict__ tgt) {
    extern __shared__ float sm[];
    const int tid = threadIdx.x;
    const int bid = blockIdx.x;

    // resident weight load (once)
    for (int idx = tid; idx < 4096; idx += TPB) {
        sm[SM_A1 + idx]  = g_A1[idx];
        sm[SM_B1 + idx]  = g_B1[idx];
        sm[SM_A2 + idx]  = g_A2[idx];
        sm[SM_B2 + idx]  = g_B2[idx];
        sm[SM_WY + idx]  = fxW1y[idx];
        sm[SM_W2X + idx] = fx_W2[idx];
        sm[SM_W2Y + idx] = fy_W2[idx];
    }
    if (tid < 64) {
        sm[SM_BX1 + tid] = fx_b1[tid];
        sm[SM_BX2 + tid] = fx_b2[tid];
        sm[SM_BY1 + tid] = fy_b1[tid];
        sm[SM_BY2 + tid] = fy_b2[tid];
    }
    __syncthreads();

    float* ys = sm + SM_YS;
    float* hs = sm + SM_HS;
    const int nl = tid >> 3;          // 0..63 (node/edge lane)
    const int c0 = (tid & 7) * 8;     // column group

    for (int it = 0; it < LOOPN; it++) {
        // ---- Phase 1: P = x@A1, Q = x@B1, agg = -inf ----
        for (int tile = bid; tile < NT_NODE; tile += NBLK) {
            int i0 = tile * 64;
            for (int idx = tid; idx < 4096; idx += TPB) {
                int n2 = idx >> 6, k = idx & 63, i = i0 + n2;
                ys[k * 65 + n2] = (i < NN) ? g_x[i * 64 + k] : 0.f;
            }
            __syncthreads();
            unsigned long long ap[4] = {0, 0, 0, 0}, aq[4] = {0, 0, 0, 0};
            #pragma unroll 8
            for (int k = 0; k < 64; k++) {
                unsigned long long xv = pack2(ys[k * 65 + nl]);
                ulonglong2 a0 = *(const ulonglong2*)&sm[SM_A1 + k * 64 + c0];
                ulonglong2 a1 = *(const ulonglong2*)&sm[SM_A1 + k * 64 + c0 + 4];
                ulonglong2 b0 = *(const ulonglong2*)&sm[SM_B1 + k * 64 + c0];
                ulonglong2 b1 = *(const ulonglong2*)&sm[SM_B1 + k * 64 + c0 + 4];
                ffma2(ap[0], xv, a0.x); ffma2(ap[1], xv, a0.y);
                ffma2(ap[2], xv, a1.x); ffma2(ap[3], xv, a1.y);
                ffma2(aq[0], xv, b0.x); ffma2(aq[1], xv, b0.y);
                ffma2(aq[2], xv, b1.x); ffma2(aq[3], xv, b1.y);
            }
            int i = i0 + nl;
            if (i < NN) {
                *(float4*)&g_P[i * 64 + c0]     = *(float4*)&ap[0];
                *(float4*)&g_P[i * 64 + c0 + 4] = *(float4*)&ap[2];
                *(float4*)&g_Q[i * 64 + c0]     = *(float4*)&aq[0];
                *(float4*)&g_Q[i * 64 + c0 + 4] = *(float4*)&aq[2];
                float4 ni = make_float4(NEG_INF, NEG_INF, NEG_INF, NEG_INF);
                *(float4*)&g_agg[i * 64 + c0]     = ni;
                *(float4*)&g_agg[i * 64 + c0 + 4] = ni;
            }
            __syncthreads();
        }
        gsync();

        // ---- Phase 2: fx edges ----
        for (int tile = bid; tile < NT_EDGE; tile += NBLK) {
            int e0 = tile * 64;
            for (int idx = tid; idx < 4096; idx += TPB) {
                int el = idx >> 6, k = idx & 63;
                ys[k * 65 + el] = g_y[(e0 + el) * 64 + k];
            }
            __syncthreads();
            int e = e0 + nl;
            int s = src[e], t = tgt[e];
            unsigned long long acc[4] = {0, 0, 0, 0};
            #pragma unroll 8
            for (int k = 0; k < 64; k++) {
                unsigned long long yv = pack2(ys[k * 65 + nl]);
                ulonglong2 w0 = *(const ulonglong2*)&sm[SM_WY + k * 64 + c0];
                ulonglong2 w1 = *(const ulonglong2*)&sm[SM_WY + k * 64 + c0 + 4];
                ffma2(acc[0], yv, w0.x); ffma2(acc[1], yv, w0.y);
                ffma2(acc[2], yv, w1.x); ffma2(acc[3], yv, w1.y);
            }
            float4 p0 = *(const float4*)&g_P[s * 64 + c0];
            float4 p1 = *(const float4*)&g_P[s * 64 + c0 + 4];
            float4 q0 = *(const float4*)&g_Q[t * 64 + c0];
            float4 q1 = *(const float4*)&g_Q[t * 64 + c0 + 4];
            const float* av = (const float*)acc;
            hs[(c0 + 0) * 65 + nl] = fmaxf(av[0] + p0.x + q0.x + sm[SM_BX1 + c0 + 0], 0.f);
            hs[(c0 + 1) * 65 + nl] = fmaxf(av[1] + p0.y + q0.y + sm[SM_BX1 + c0 + 1], 0.f);
            hs[(c0 + 2) * 65 + nl] = fmaxf(av[2] + p0.z + q0.z + sm[SM_BX1 + c0 + 2], 0.f);
            hs[(c0 + 3) * 65 + nl] = fmaxf(av[3] + p0.w + q0.w + sm[SM_BX1 + c0 + 3], 0.f);
            hs[(c0 + 4) * 65 + nl] = fmaxf(av[4] + p1.x + q1.x + sm[SM_BX1 + c0 + 4], 0.f);
            hs[(c0 + 5) * 65 + nl] = fmaxf(av[5] + p1.y + q1.y + sm[SM_BX1 + c0 + 5], 0.f);
            hs[(c0 + 6) * 65 + nl] = fmaxf(av[6] + p1.z + q1.z + sm[SM_BX1 + c0 + 6], 0.f);
            hs[(c0 + 7) * 65 + nl] = fmaxf(av[7] + p1.w + q1.w + sm[SM_BX1 + c0 + 7], 0.f);
            __syncthreads();
            acc[0] = *(const unsigned long long*)&sm[SM_BX2 + c0];
            acc[1] = *(const unsigned long long*)&sm[SM_BX2 + c0 + 2];
            acc[2] = *(const unsigned long long*)&sm[SM_BX2 + c0 + 4];
            acc[3] = *(const unsigned long long*)&sm[SM_BX2 + c0 + 6];
            #pragma unroll 8
            for (int k = 0; k < 64; k++) {
                unsigned long long hv = pack2(hs[k * 65 + nl]);
                ulonglong2 w0 = *(const ulonglong2*)&sm[SM_W2X + k * 64 + c0];
                ulonglong2 w1 = *(const ulonglong2*)&sm[SM_W2X + k * 64 + c0 + 4];
                ffma2(acc[0], hv, w0.x); ffma2(acc[1], hv, w0.y);
                ffma2(acc[2], hv, w1.x); ffma2(acc[3], hv, w1.y);
            }
            #pragma unroll
            for (int j = 0; j < 8; j++)
                atomicMaxFloat(&g_agg[t * 64 + c0 + j], ((const float*)acc)[j]);
        }
        gsync();

        // ---- Phase 3: x = max(x, fix(agg)); P = x@A2, Q = x@B2 ----
        for (int tile = bid; tile < NT_NODE; tile += NBLK) {
            int i0 = tile * 64;
            int i = i0 + nl;
            if (i < NN) {
                float4 a0 = *(const float4*)&g_agg[i * 64 + c0];
                float4 a1 = *(const float4*)&g_agg[i * 64 + c0 + 4];
                float4 x0 = *(const float4*)&g_x[i * 64 + c0];
                float4 x1 = *(const float4*)&g_x[i * 64 + c0 + 4];
                float xn[8];
                xn[0] = fmaxf(x0.x, (a0.x == NEG_INF) ? 0.f : a0.x);
                xn[1] = fmaxf(x0.y, (a0.y == NEG_INF) ? 0.f : a0.y);
                xn[2] = fmaxf(x0.z, (a0.z == NEG_INF) ? 0.f : a0.z);
                xn[3] = fmaxf(x0.w, (a0.w == NEG_INF) ? 0.f : a0.w);
                xn[4] = fmaxf(x1.x, (a1.x == NEG_INF) ? 0.f : a1.x);
                xn[5] = fmaxf(x1.y, (a1.y == NEG_INF) ? 0.f : a1.y);
                xn[6] = fmaxf(x1.z, (a1.z == NEG_INF) ? 0.f : a1.z);
                xn[7] = fmaxf(x1.w, (a1.w == NEG_INF) ? 0.f : a1.w);
                *(float4*)&g_x[i * 64 + c0]     = make_float4(xn[0], xn[1], xn[2], xn[3]);
                *(float4*)&g_x[i * 64 + c0 + 4] = make_float4(xn[4], xn[5], xn[6], xn[7]);
                #pragma unroll
                for (int j = 0; j < 8; j++) ys[(c0 + j) * 65 + nl] = xn[j];
            } else {
                #pragma unroll
                for (int j = 0; j < 8; j++) ys[(c0 + j) * 65 + nl] = 0.f;
            }
            __syncthreads();
            unsigned long long ap[4] = {0, 0, 0, 0}, aq[4] = {0, 0, 0, 0};
            #pragma unroll 8
            for (int k = 0; k < 64; k++) {
                unsigned long long xv = pack2(ys[k * 65 + nl]);
                ulonglong2 a0 = *(const ulonglong2*)&sm[SM_A2 + k * 64 + c0];
                ulonglong2 a1 = *(const ulonglong2*)&sm[SM_A2 + k * 64 + c0 + 4];
                ulonglong2 b0 = *(const ulonglong2*)&sm[SM_B2 + k * 64 + c0];
                ulonglong2 b1 = *(const ulonglong2*)&sm[SM_B2 + k * 64 + c0 + 4];
                ffma2(ap[0], xv, a0.x); ffma2(ap[1], xv, a0.y);
                ffma2(ap[2], xv, a1.x); ffma2(ap[3], xv, a1.y);
                ffma2(aq[0], xv, b0.x); ffma2(aq[1], xv, b0.y);
                ffma2(aq[2], xv, b1.x); ffma2(aq[3], xv, b1.y);
            }
            if (i < NN) {
                *(float4*)&g_P[i * 64 + c0]     = *(float4*)&ap[0];
                *(float4*)&g_P[i * 64 + c0 + 4] = *(float4*)&ap[2];
                *(float4*)&g_Q[i * 64 + c0]     = *(float4*)&aq[0];
                *(float4*)&g_Q[i * 64 + c0 + 4] = *(float4*)&aq[2];
            }
            __syncthreads();
        }
        gsync();

        // ---- Phase 4: fy edges: y = max(y, mlp(P[tgt] + Q[src])) ----
        for (int tile = bid; tile < NT_EDGE; tile += NBLK) {
            int e0 = tile * 64;
            int e = e0 + nl;
            int s = src[e], t = tgt[e];
            float4 p0 = *(const float4*)&g_P[t * 64 + c0];
            float4 p1 = *(const float4*)&g_P[t * 64 + c0 + 4];
            float4 q0 = *(const float4*)&g_Q[s * 64 + c0];
            float4 q1 = *(const float4*)&g_Q[s * 64 + c0 + 4];
            hs[(c0 + 0) * 65 + nl] = fmaxf(p0.x + q0.x + sm[SM_BY1 + c0 + 0], 0.f);
            hs[(c0 + 1) * 65 + nl] = fmaxf(p0.y + q0.y + sm[SM_BY1 + c0 + 1], 0.f);
            hs[(c0 + 2) * 65 + nl] = fmaxf(p0.z + q0.z + sm[SM_BY1 + c0 + 2], 0.f);
            hs[(c0 + 3) * 65 + nl] = fmaxf(p0.w + q0.w + sm[SM_BY1 + c0 + 3], 0.f);
            hs[(c0 + 4) * 65 + nl] = fmaxf(p1.x + q1.x + sm[SM_BY1 + c0 + 4], 0.f);
            hs[(c0 + 5) * 65 + nl] = fmaxf(p1.y + q1.y + sm[SM_BY1 + c0 + 5], 0.f);
            hs[(c0 + 6) * 65 + nl] = fmaxf(p1.z + q1.z + sm[SM_BY1 + c0 + 6], 0.f);
            hs[(c0 + 7) * 65 + nl] = fmaxf(p1.w + q1.w + sm[SM_BY1 + c0 + 7], 0.f);
            __syncthreads();
            unsigned long long acc[4];
            acc[0] = *(const unsigned long long*)&sm[SM_BY2 + c0];
            acc[1] = *(const unsigned long long*)&sm[SM_BY2 + c0 + 2];
            acc[2] = *(const unsigned long long*)&sm[SM_BY2 + c0 + 4];
            acc[3] = *(const unsigned long long*)&sm[SM_BY2 + c0 + 6];
            #pragma unroll 8
            for (int k = 0; k < 64; k++) {
                unsigned long long hv = pack2(hs[k * 65 + nl]);
                ulonglong2 w0 = *(const ulonglong2*)&sm[SM_W2Y + k * 64 + c0];
                ulonglong2 w1 = *(const ulonglong2*)&sm[SM_W2Y + k * 64 + c0 + 4];
                ffma2(acc[0], hv, w0.x); ffma2(acc[1], hv, w0.y);
                ffma2(acc[2], hv, w1.x); ffma2(acc[3], hv, w1.y);
            }
            float4 y0 = *(const float4*)&g_y[e * 64 + c0];
            float4 y1 = *(const float4*)&g_y[e * 64 + c0 + 4];
            const float* av = (const float*)acc;
            y0.x = fmaxf(y0.x, av[0]); y0.y = fmaxf(y0.y, av[1]);
            y0.z = fmaxf(y0.z, av[2]); y0.w = fmaxf(y0.w, av[3]);
            y1.x = fmaxf(y1.x, av[4]); y1.y = fmaxf(y1.y, av[5]);
            y1.z = fmaxf(y1.z, av[6]); y1.w = fmaxf(y1.w, av[7]);
            *(float4*)&g_y[e * 64 + c0]     = y0;
            *(float4*)&g_y[e * 64 + c0 + 4] = y1;
            __syncthreads();
        }
        gsync();
    }
}

// ---------------- output kernels ----------------
__global__ void k_winner_init() {
    int i = blockIdx.x * blockDim.x + threadIdx.x;
    if (i < NN * NN) g_winner[i] = -1;
}

__global__ void k_winner(const int* __restrict__ src, const int* __restrict__ tgt) {
    int e = blockIdx.x * blockDim.x + threadIdx.x;
    if (e < NEDGE) atomicMax(&g_winner[src[e] * NN + tgt[e]], e);
}

__global__ void k_scatter(const int* __restrict__ src, const int* __restrict__ tgt,
                          float* __restrict__ out) {
    int idx = blockIdx.x * blockDim.x + threadIdx.x;
    if (idx < NEDGE * EDIM) {
        int e = idx >> 6, c = idx & 63;
        int s = src[e], t = tgt[e];
        long long slot = (long long)s * NN + t;
        if (g_winner[slot] == e) out[slot * 64 + c] = g_y[idx];
    }
}

__global__ void k_out_x(float* __restrict__ out) {
    int i = blockIdx.x * blockDim.x + threadIdx.x;
    if (i < NN * EDIM) out[(long long)NN * NN * EDIM + i] = g_x[i];
}

// ---------------- launch ----------------
extern "C" void kernel_launch(void* const* d_in, const int* in_sizes, int n_in,
                              void* d_out, int out_size) {
    const float* v      = (const float*)d_in[0];
    const float* labels = (const float*)d_in[1];
    const int*   ei     = (const int*)d_in[4];
    const float* hx_W1 = (const float*)d_in[6],  *hx_b1 = (const float*)d_in[7];
    const float* hx_W2 = (const float*)d_in[8],  *hx_b2 = (const float*)d_in[9];
    const float* hy_W1 = (const float*)d_in[10], *hy_b1 = (const float*)d_in[11];
    const float* hy_W2 = (const float*)d_in[12], *hy_b2 = (const float*)d_in[13];
    const float* fx_W1 = (const float*)d_in[14], *fx_b1 = (const float*)d_in[15];
    const float* fx_W2 = (const float*)d_in[16], *fx_b2 = (const float*)d_in[17];
    const float* fy_W1 = (const float*)d_in[18], *fy_b1 = (const float*)d_in[19];
    const float* fy_W2 = (const float*)d_in[20], *fy_b2 = (const float*)d_in[21];

    const int* src = ei;
    const int* tgt = ei + NEDGE;
    float* out = (float*)d_out;

    cudaFuncSetAttribute(k_loop, cudaFuncAttributeMaxDynamicSharedMemorySize,
                         SM_FLOATS * sizeof(float));

    // fork a side stream for the big memset + winner machinery (overlaps loop)
    cudaStream_t s2;
    cudaStreamCreateWithFlags(&s2, cudaStreamNonBlocking);
    cudaEvent_t evFork, evJoin;
    cudaEventCreateWithFlags(&evFork, cudaEventDisableTiming);
    cudaEventCreateWithFlags(&evJoin, cudaEventDisableTiming);

    cudaEventRecord(evFork, 0);
    cudaStreamWaitEvent(s2, evFork, 0);
    cudaMemsetAsync(d_out, 0, (size_t)NN * NN * EDIM * sizeof(float), s2);
    k_winner_init<<<(NN * NN + 255) / 256, 256, 0, s2>>>();
    k_winner<<<(NEDGE + 255) / 256, 256, 0, s2>>>(src, tgt);
    cudaEventRecord(evJoin, s2);

    // main stream: prelude
    k_vc<<<(NN + 255) / 256, 256>>>(v, labels);
    k_goal<<<1, 256>>>(labels);
    k_wprep<<<16, 256>>>(fx_W1, fy_W1, hy_W1);
    k_init_x<<<NN, 64>>>(hx_W1, hx_b1, hx_W2, hx_b2);
    k_node8<<<NN, 64>>>();
    k_edge_y0<<<NEDGE / 32, 256>>>(hy_b1, hy_W2, hy_b2, src, tgt);

    // fused 10-iteration loop (one persistent kernel, grid barriers inside)
    k_loop<<<NBLK, TPB, SM_FLOATS * sizeof(float)>>>(
        fx_W1 + 192 * 64, fx_b1, fx_W2, fx_b2, fy_b1, fy_W2, fy_b2, src, tgt);

    // join side stream, then output
    cudaStreamWaitEvent(0, evJoin, 0);
    k_scatter<<<(NEDGE * EDIM + 255) / 256, 256>>>(src, tgt, out);
    k_out_x<<<(NN * EDIM + 255) / 256, 256>>>(out);
}